// round 10
// baseline (speedup 1.0000x reference)
#include <cuda_runtime.h>

// Triplet margin loss, B=65536 rows, D=256 floats per row.
// HBM-bound streaming: 3 x 67MB reads, plateau ~6.0 TB/s so far.
// R10 experiment: split the 6 LDG.128 per warp into TWO batches of 3 with a
// forced SASS-level dependency (volatile mov.b64 of batch-2 pointers consumes
// batch-1 partials). MLP_p1 drops 6 -> 3, halving per-CTA burst depth into
// the shared L1tex wavefront queue (oe*MLP_p1: 48 -> 24) while SM-wide
// outstanding loads (64 warps x 3) still cover DRAM latency.
// Base = best-kernel config: plain cached loads, 256-thread blocks,
// fence-free packed-atomic finalize (count + fixed-point sum in one 64-bit
// atomicAdd; no __threadfence -> no CCTL.IVALL).

static constexpr int B = 65536;
static constexpr int D4 = 64;            // 256 floats = 64 float4
static constexpr int WARPS_PER_BLOCK = 8;
static constexpr int THREADS = WARPS_PER_BLOCK * 32;
static constexpr int BLOCKS = B / WARPS_PER_BLOCK;   // 8192

static constexpr int COUNT_SHIFT = 50;
// Max sum: ~1.3e11 * 256 = 3.4e13 < 2^50. Count max 8192 fits in [50:63].

// Zero at module load; last block resets it each launch (deterministic replays).
__device__ unsigned long long g_acc = 0ull;

__global__ void __launch_bounds__(THREADS)
triplet_loss_kernel(const float4* __restrict__ a,
                    const float4* __restrict__ p,
                    const float4* __restrict__ n,
                    float* __restrict__ out,
                    float inv_b) {
    const int warp_in_block = threadIdx.x >> 5;
    const int lane = threadIdx.x & 31;
    const long long row = (long long)blockIdx.x * WARPS_PER_BLOCK + warp_in_block;

    const float4* ar = a + row * D4;
    const float4* pr = p + row * D4;
    const float4* nr = n + row * D4;

    // ---- Batch 1: 3 LDG.128 (first half of each tensor row) ----
    float4 a0 = ar[lane];
    float4 p0 = pr[lane];
    float4 n0 = nr[lane];

    float dap2 = 0.f, dan2 = 0.f, dpn2 = 0.f;
    {
        float d;
        d = a0.x - p0.x; dap2 += d * d;
        d = a0.y - p0.y; dap2 += d * d;
        d = a0.z - p0.z; dap2 += d * d;
        d = a0.w - p0.w; dap2 += d * d;

        d = a0.x - n0.x; dan2 += d * d;
        d = a0.y - n0.y; dan2 += d * d;
        d = a0.z - n0.z; dan2 += d * d;
        d = a0.w - n0.w; dan2 += d * d;

        d = p0.x - n0.x; dpn2 += d * d;
        d = p0.y - n0.y; dpn2 += d * d;
        d = p0.z - n0.z; dpn2 += d * d;
        d = p0.w - n0.w; dpn2 += d * d;
    }

    // ---- Forced dependency: batch-2 addresses consume batch-1 partials ----
    // Volatile asm so neither NVVM nor ptxas can hoist the second load batch
    // above the FFMA chain (keeps MLP_p1 = 3 in SASS).
    const float4 *ar2, *pr2, *nr2;
    asm volatile("mov.b64 %0, %1;" : "=l"(ar2) : "l"(ar + lane + 32), "f"(dap2));
    asm volatile("mov.b64 %0, %1;" : "=l"(pr2) : "l"(pr + lane + 32), "f"(dan2));
    asm volatile("mov.b64 %0, %1;" : "=l"(nr2) : "l"(nr + lane + 32), "f"(dpn2));

    // ---- Batch 2: 3 LDG.128 (second half of each tensor row) ----
    float4 a1 = *ar2;
    float4 p1 = *pr2;
    float4 n1 = *nr2;

    {
        float d;
        d = a1.x - p1.x; dap2 += d * d;
        d = a1.y - p1.y; dap2 += d * d;
        d = a1.z - p1.z; dap2 += d * d;
        d = a1.w - p1.w; dap2 += d * d;

        d = a1.x - n1.x; dan2 += d * d;
        d = a1.y - n1.y; dan2 += d * d;
        d = a1.z - n1.z; dan2 += d * d;
        d = a1.w - n1.w; dan2 += d * d;

        d = p1.x - n1.x; dpn2 += d * d;
        d = p1.y - n1.y; dpn2 += d * d;
        d = p1.z - n1.z; dpn2 += d * d;
        d = p1.w - n1.w; dpn2 += d * d;
    }

    // Warp reduce the three partial sums.
    #pragma unroll
    for (int off = 16; off > 0; off >>= 1) {
        dap2 += __shfl_xor_sync(0xFFFFFFFFu, dap2, off);
        dan2 += __shfl_xor_sync(0xFFFFFFFFu, dan2, off);
        dpn2 += __shfl_xor_sync(0xFFFFFFFFu, dpn2, off);
    }

    __shared__ float warp_loss[WARPS_PER_BLOCK];
    if (lane == 0) {
        float dap = sqrtf(dap2);
        float dan = sqrtf(dan2);
        float dpn = sqrtf(dpn2);
        float margin_sim    = 1.0f + 2.0f / (expf(4.0f * dap) + 1e-6f);
        float margin_dissim = 1.0f + 2.0f / (expf(4.0f - 4.0f * dan) + 1e-6f);
        float loss = dap - 0.5f * (dan + dpn) + margin_sim + margin_dissim;
        warp_loss[warp_in_block] = loss;
    }
    __syncthreads();

    if (threadIdx.x == 0) {
        float s = 0.f;
        #pragma unroll
        for (int i = 0; i < WARPS_PER_BLOCK; i++) s += warp_loss[i];

        // Fixed-point contribution: strictly positive (~1.6e7 per block).
        unsigned long long fixed = __float2ull_rn(s * 256.0f);
        unsigned long long contrib = (1ull << COUNT_SHIFT) + fixed;
        unsigned long long prev = atomicAdd(&g_acc, contrib);

        if ((prev >> COUNT_SHIFT) == (unsigned long long)(BLOCKS - 1)) {
            // Last arrival: prev+contrib holds the full count and full sum.
            unsigned long long total_fixed =
                (prev + contrib) & ((1ull << COUNT_SHIFT) - 1ull);
            out[0] = (float)((double)total_fixed * (1.0 / 256.0)) * inv_b;
            // Reset for the next graph replay (no concurrent writers remain).
            atomicExch(&g_acc, 0ull);
        }
    }
}

extern "C" void kernel_launch(void* const* d_in, const int* in_sizes, int n_in,
                              void* d_out, int out_size) {
    const float4* a = (const float4*)d_in[0];
    const float4* p = (const float4*)d_in[1];
    const float4* n = (const float4*)d_in[2];
    float* out = (float*)d_out;

    triplet_loss_kernel<<<BLOCKS, THREADS>>>(a, p, n, out, 1.0f / (float)B);
}

// round 11
// speedup vs baseline: 1.2376x; 1.2376x over previous
#include <cuda_runtime.h>

// Triplet margin loss, B=65536 rows, D=256 floats per row.
// HBM-bound streaming: 3 x 67MB reads, plateau ~6.0 TB/s so far.
// R11 experiment: 256-bit vector loads (ld.global.v8.f32, sm_100+).
// One row = 1024B = 32 lanes x 32B, so each warp covers a whole row of each
// tensor with ONE v8 load -> 3 wide loads per warp (vs 6 x LDG.128), halving
// L1tex wavefront-issue count per byte at identical bytes-in-flight.
// Epilogue unchanged from the best kernel: warp shuffle reduce, 8 warps/block,
// fence-free packed-atomic finalize (count + fixed-point sum in one 64-bit
// atomicAdd; no __threadfence -> no CCTL.IVALL).

static constexpr int B = 65536;
static constexpr int D = 256;            // floats per row
static constexpr int WARPS_PER_BLOCK = 8;
static constexpr int THREADS = WARPS_PER_BLOCK * 32;
static constexpr int BLOCKS = B / WARPS_PER_BLOCK;   // 8192

static constexpr int COUNT_SHIFT = 50;
// Max sum: ~1.3e11 * 256 = 3.4e13 < 2^50. Count max 8192 fits in [50:63].

// Zero at module load; last block resets it each launch (deterministic replays).
__device__ unsigned long long g_acc = 0ull;

// 256-bit global load (LDG.E.256 on sm_100+/sm_103a).
__device__ __forceinline__ void ldg256(float r[8], const float* ptr) {
    asm("ld.global.v8.f32 {%0,%1,%2,%3,%4,%5,%6,%7}, [%8];"
        : "=f"(r[0]), "=f"(r[1]), "=f"(r[2]), "=f"(r[3]),
          "=f"(r[4]), "=f"(r[5]), "=f"(r[6]), "=f"(r[7])
        : "l"(ptr));
}

__global__ void __launch_bounds__(THREADS)
triplet_loss_kernel(const float* __restrict__ a,
                    const float* __restrict__ p,
                    const float* __restrict__ n,
                    float* __restrict__ out,
                    float inv_b) {
    const int warp_in_block = threadIdx.x >> 5;
    const int lane = threadIdx.x & 31;
    const long long row = (long long)blockIdx.x * WARPS_PER_BLOCK + warp_in_block;
    const long long off = row * D + lane * 8;

    // Front-batch 3 x 256-bit loads (96B per thread in flight).
    float A[8], P[8], N[8];
    ldg256(A, a + off);
    ldg256(P, p + off);
    ldg256(N, n + off);

    float dap2 = 0.f, dan2 = 0.f, dpn2 = 0.f;
    #pragma unroll
    for (int i = 0; i < 8; i++) {
        float d1 = A[i] - P[i]; dap2 += d1 * d1;
        float d2 = A[i] - N[i]; dan2 += d2 * d2;
        float d3 = P[i] - N[i]; dpn2 += d3 * d3;
    }

    // Warp reduce the three partial sums.
    #pragma unroll
    for (int off2 = 16; off2 > 0; off2 >>= 1) {
        dap2 += __shfl_xor_sync(0xFFFFFFFFu, dap2, off2);
        dan2 += __shfl_xor_sync(0xFFFFFFFFu, dan2, off2);
        dpn2 += __shfl_xor_sync(0xFFFFFFFFu, dpn2, off2);
    }

    __shared__ float warp_loss[WARPS_PER_BLOCK];
    if (lane == 0) {
        float dap = sqrtf(dap2);
        float dan = sqrtf(dan2);
        float dpn = sqrtf(dpn2);
        float margin_sim    = 1.0f + 2.0f / (expf(4.0f * dap) + 1e-6f);
        float margin_dissim = 1.0f + 2.0f / (expf(4.0f - 4.0f * dan) + 1e-6f);
        float loss = dap - 0.5f * (dan + dpn) + margin_sim + margin_dissim;
        warp_loss[warp_in_block] = loss;
    }
    __syncthreads();

    if (threadIdx.x == 0) {
        float s = 0.f;
        #pragma unroll
        for (int i = 0; i < WARPS_PER_BLOCK; i++) s += warp_loss[i];

        // Fixed-point contribution: strictly positive (~1.6e7 per block).
        unsigned long long fixed = __float2ull_rn(s * 256.0f);
        unsigned long long contrib = (1ull << COUNT_SHIFT) + fixed;
        unsigned long long prev = atomicAdd(&g_acc, contrib);

        if ((prev >> COUNT_SHIFT) == (unsigned long long)(BLOCKS - 1)) {
            // Last arrival: prev+contrib holds the full count and full sum.
            unsigned long long total_fixed =
                (prev + contrib) & ((1ull << COUNT_SHIFT) - 1ull);
            out[0] = (float)((double)total_fixed * (1.0 / 256.0)) * inv_b;
            // Reset for the next graph replay (no concurrent writers remain).
            atomicExch(&g_acc, 0ull);
        }
    }
}

extern "C" void kernel_launch(void* const* d_in, const int* in_sizes, int n_in,
                              void* d_out, int out_size) {
    const float* a = (const float*)d_in[0];
    const float* p = (const float*)d_in[1];
    const float* n = (const float*)d_in[2];
    float* out = (float*)d_out;

    triplet_loss_kernel<<<BLOCKS, THREADS>>>(a, p, n, out, 1.0f / (float)B);
}

// round 12
// speedup vs baseline: 1.2471x; 1.0077x over previous
#include <cuda_runtime.h>

// Triplet margin loss, B=65536 rows, D=256 floats per row.
// HBM-bound streaming: 3 x 67MB reads at ~6.1 TB/s.
// R12: 256-bit STREAMING loads (ld.global.cs.v8.f32 -> LDG.E.256.CS).
// One row = 1024B = 32 lanes x 32B: each warp covers a whole row of each
// tensor with ONE v8 load -> 3 wide evict-first loads per warp.
// Epilogue: warp shuffle reduce, 8 warps/block, fence-free packed-atomic
// finalize (count + fixed-point sum in one 64-bit atomicAdd; no
// __threadfence -> no CCTL.IVALL).

static constexpr int B = 65536;
static constexpr int D = 256;            // floats per row
static constexpr int WARPS_PER_BLOCK = 8;
static constexpr int THREADS = WARPS_PER_BLOCK * 32;
static constexpr int BLOCKS = B / WARPS_PER_BLOCK;   // 8192

static constexpr int COUNT_SHIFT = 50;
// Max sum: ~1.3e11 * 256 = 3.4e13 < 2^50. Count max 8192 fits in [50:63].

// Zero at module load; last block resets it each launch (deterministic replays).
__device__ unsigned long long g_acc = 0ull;

// 256-bit streaming (evict-first) global load on sm_100+/sm_103a.
__device__ __forceinline__ void ldg256cs(float r[8], const float* ptr) {
    asm("ld.global.cs.v8.f32 {%0,%1,%2,%3,%4,%5,%6,%7}, [%8];"
        : "=f"(r[0]), "=f"(r[1]), "=f"(r[2]), "=f"(r[3]),
          "=f"(r[4]), "=f"(r[5]), "=f"(r[6]), "=f"(r[7])
        : "l"(ptr));
}

__global__ void __launch_bounds__(THREADS)
triplet_loss_kernel(const float* __restrict__ a,
                    const float* __restrict__ p,
                    const float* __restrict__ n,
                    float* __restrict__ out,
                    float inv_b) {
    const int warp_in_block = threadIdx.x >> 5;
    const int lane = threadIdx.x & 31;
    const long long row = (long long)blockIdx.x * WARPS_PER_BLOCK + warp_in_block;
    const long long off = row * D + lane * 8;

    // Front-batch 3 x 256-bit streaming loads (96B per thread in flight).
    float A[8], P[8], N[8];
    ldg256cs(A, a + off);
    ldg256cs(P, p + off);
    ldg256cs(N, n + off);

    float dap2 = 0.f, dan2 = 0.f, dpn2 = 0.f;
    #pragma unroll
    for (int i = 0; i < 8; i++) {
        float d1 = A[i] - P[i]; dap2 += d1 * d1;
        float d2 = A[i] - N[i]; dan2 += d2 * d2;
        float d3 = P[i] - N[i]; dpn2 += d3 * d3;
    }

    // Warp reduce the three partial sums.
    #pragma unroll
    for (int off2 = 16; off2 > 0; off2 >>= 1) {
        dap2 += __shfl_xor_sync(0xFFFFFFFFu, dap2, off2);
        dan2 += __shfl_xor_sync(0xFFFFFFFFu, dan2, off2);
        dpn2 += __shfl_xor_sync(0xFFFFFFFFu, dpn2, off2);
    }

    __shared__ float warp_loss[WARPS_PER_BLOCK];
    if (lane == 0) {
        float dap = sqrtf(dap2);
        float dan = sqrtf(dan2);
        float dpn = sqrtf(dpn2);
        float margin_sim    = 1.0f + 2.0f / (expf(4.0f * dap) + 1e-6f);
        float margin_dissim = 1.0f + 2.0f / (expf(4.0f - 4.0f * dan) + 1e-6f);
        float loss = dap - 0.5f * (dan + dpn) + margin_sim + margin_dissim;
        warp_loss[warp_in_block] = loss;
    }
    __syncthreads();

    if (threadIdx.x == 0) {
        float s = 0.f;
        #pragma unroll
        for (int i = 0; i < WARPS_PER_BLOCK; i++) s += warp_loss[i];

        // Fixed-point contribution: strictly positive (~1.6e7 per block).
        unsigned long long fixed = __float2ull_rn(s * 256.0f);
        unsigned long long contrib = (1ull << COUNT_SHIFT) + fixed;
        unsigned long long prev = atomicAdd(&g_acc, contrib);

        if ((prev >> COUNT_SHIFT) == (unsigned long long)(BLOCKS - 1)) {
            // Last arrival: prev+contrib holds the full count and full sum.
            unsigned long long total_fixed =
                (prev + contrib) & ((1ull << COUNT_SHIFT) - 1ull);
            out[0] = (float)((double)total_fixed * (1.0 / 256.0)) * inv_b;
            // Reset for the next graph replay (no concurrent writers remain).
            atomicExch(&g_acc, 0ull);
        }
    }
}

extern "C" void kernel_launch(void* const* d_in, const int* in_sizes, int n_in,
                              void* d_out, int out_size) {
    const float* a = (const float*)d_in[0];
    const float* p = (const float*)d_in[1];
    const float* n = (const float*)d_in[2];
    float* out = (float*)d_out;

    triplet_loss_kernel<<<BLOCKS, THREADS>>>(a, p, n, out, 1.0f / (float)B);
}